// round 15
// baseline (speedup 1.0000x reference)
#include <cuda_runtime.h>
#include <cuda_fp16.h>
#include <cstdint>
#include <math.h>

// Problem constants
#define BATCH 2
#define SEQ   2048
#define EMB   2048
#define NH    16
#define HDIM  128
#define E3    6144

#define SM_SCALE 0.08838834764831845f
#define PERSIST_CTAS 296

// ---------------------------------------------------------------------------
// Scratch (__device__ globals; allocation-free rule)
// ---------------------------------------------------------------------------
__device__ __half g_xh[(size_t)BATCH * SEQ * EMB];
__device__ __half g_wah[(size_t)E3 * EMB];                         // W_attn^T hi
__device__ __half g_qkh[(size_t)BATCH * SEQ * E3];                 // q hi | k hi
__device__ __half g_vth[(size_t)BATCH * NH * HDIM * SEQ];          // V^T hi
__device__ __half g_yh[(size_t)BATCH * SEQ * EMB];
__device__ __half g_wph[(size_t)EMB * EMB];                        // W_proj^T hi
__device__ float  g_cos[(size_t)BATCH * SEQ * 64];                 // RoPE tables
__device__ float  g_sin[(size_t)BATCH * SEQ * 64];

// ---------------------------------------------------------------------------
// PTX helpers (arch-generic: cp.async, ldmatrix, mma.sync)
// ---------------------------------------------------------------------------
__device__ __forceinline__ uint32_t smem_u32(const void* p) {
    uint32_t a;
    asm("{ .reg .u64 t; cvta.to.shared.u64 t, %1; cvt.u32.u64 %0, t; }"
        : "=r"(a) : "l"(p));
    return a;
}
#define CP16(dst, src) \
    asm volatile("cp.async.cg.shared.global [%0], [%1], 16;" :: "r"(dst), "l"(src))
#define CP_COMMIT() asm volatile("cp.async.commit_group;" ::: "memory")
#define CP_WAIT0()  asm volatile("cp.async.wait_group 0;" ::: "memory")
#define CP_WAIT1()  asm volatile("cp.async.wait_group 1;" ::: "memory")
#define CP_WAIT2()  asm volatile("cp.async.wait_group 2;" ::: "memory")

__device__ __forceinline__ void ldsm_x4(uint32_t* r, uint32_t a) {
    asm volatile("ldmatrix.sync.aligned.m8n8.x4.shared.b16 {%0,%1,%2,%3}, [%4];"
        : "=r"(r[0]), "=r"(r[1]), "=r"(r[2]), "=r"(r[3]) : "r"(a));
}
__device__ __forceinline__ void mma16816h(float* d, const uint32_t* a,
                                          const uint32_t* b) {
    asm volatile(
        "mma.sync.aligned.m16n8k16.row.col.f32.f16.f16.f32 "
        "{%0,%1,%2,%3}, {%4,%5,%6,%7}, {%8,%9}, {%0,%1,%2,%3};"
        : "+f"(d[0]), "+f"(d[1]), "+f"(d[2]), "+f"(d[3])
        : "r"(a[0]), "r"(a[1]), "r"(a[2]), "r"(a[3]), "r"(b[0]), "r"(b[1]));
}

// ---------------------------------------------------------------------------
// GEMM tile geometry (BK=64): 128 rows x 64 fp16 = 128B rows.
// Swizzle: chunk' = chunk ^ (row & 7).
// ---------------------------------------------------------------------------
#define GROW_B  128
#define GTILE_B 16384
#define STB     (2 * GTILE_B)        // stage bytes (Ah, Bh) = 32 KB
#define GSMEM   (3 * STB)            // 96 KB; also >= 128*129*4 epilogue staging

// ===========================================================================
// Shared GEMM mainloop (single product Ah*Bh, BK=64): computes acc[4][4][4].
// Expanded inside a per-tile scope; bm/bn must be in scope.
// ===========================================================================
#define GEMM_MAINLOOP(Ah, Bh, K, lda, ldb)                                   \
    const long long ldaL = (lda), ldbL = (ldb);                              \
    const __half* pA = (Ah) + (bm + lr0) * ldaL + lc * 8;                    \
    const __half* pB = (Bh) + (bn + lr0) * ldbL + lc * 8;                    \
    const int nt = (K) >> 6;                                                 \
    ISSUE_STAGE(sb);                                                         \
    CP_COMMIT();                                                             \
    ISSUE_STAGE(sb + STB);                                                   \
    CP_COMMIT();                                                             \
    float acc[4][4][4];                                                      \
    _Pragma("unroll")                                                        \
    for (int i = 0; i < 4; ++i)                                              \
        _Pragma("unroll")                                                    \
        for (int j = 0; j < 4; ++j)                                          \
            _Pragma("unroll")                                                \
            for (int k = 0; k < 4; ++k) acc[i][j][k] = 0.f;                  \
    uint32_t cur_st = sb;                                                    \
    uint32_t iss_st = sb + 2 * STB;                                          \
    for (int t = 0; t < nt; ++t) {                                           \
        CP_WAIT1();                                                          \
        __syncthreads();                                                     \
        if (t + 2 < nt) ISSUE_STAGE(iss_st);                                 \
        CP_COMMIT();                                                         \
        const uint32_t pAs = cur_st, pBs = cur_st + GTILE_B;                 \
        _Pragma("unroll")                                                    \
        for (int k16 = 0; k16 < 4; ++k16) {                                  \
            const uint32_t kx = (uint32_t)(k16 << 5);                        \
            uint32_t fBh[2][4];                                              \
            _Pragma("unroll")                                                \
            for (int bt = 0; bt < 2; ++bt)                                   \
                ldsm_x4(fBh[bt], pBs + ((b_base + bt * (16 * GROW_B)) ^ kx));\
            _Pragma("unroll")                                                \
            for (int mt = 0; mt < 4; ++mt) {                                 \
                uint32_t fAh[4];                                             \
                ldsm_x4(fAh, pAs + ((a_base + mt * (16 * GROW_B)) ^ kx));    \
                _Pragma("unroll")                                            \
                for (int n8 = 0; n8 < 4; ++n8) {                             \
                    const uint32_t* bh = &fBh[n8 >> 1][(n8 & 1) << 1];       \
                    mma16816h(acc[mt][n8], fAh, bh);                         \
                }                                                            \
            }                                                                \
        }                                                                    \
        uint32_t nxt = cur_st + STB;                                         \
        if (nxt >= sb + 3 * STB) nxt = sb;                                   \
        cur_st = nxt;                                                        \
        nxt = iss_st + STB;                                                  \
        if (nxt >= sb + 3 * STB) nxt = sb;                                   \
        iss_st = nxt;                                                        \
    }

#define ISSUE_STAGE(st)                                                      \
    do {                                                                     \
        _Pragma("unroll")                                                    \
        for (int jj = 0; jj < 4; ++jj) {                                     \
            CP16((st) + ldst + jj * (32 * GROW_B), pA + jj * 32LL * ldaL);   \
            CP16((st) + GTILE_B + ldst + jj * (32 * GROW_B),                 \
                 pB + jj * 32LL * ldbL);                                     \
        }                                                                    \
        pA += 64; pB += 64;                                                  \
    } while (0)

// Per-kernel tile-independent index setup (tid-dependent only)
#define GEMM_IDX_SETUP()                                                     \
    const int tid  = threadIdx.x;                                            \
    const int wid  = tid >> 5, lane = tid & 31;                              \
    const int wm   = wid & 1;                                                \
    const int wn   = wid >> 1;                                               \
    const uint32_t sb = smem_u32(smem);                                      \
    const int lr0 = tid >> 3;                                                \
    const int lc  = tid & 7;                                                 \
    const uint32_t ldst =                                                    \
        (uint32_t)lr0 * GROW_B + (((uint32_t)lc ^ (lr0 & 7)) << 4);          \
    const int row_a = wm * 64 + (lane & 15);                                 \
    const uint32_t a_base = (uint32_t)row_a * GROW_B +                       \
        ((((uint32_t)lane >> 4) ^ ((uint32_t)row_a & 7)) << 4);              \
    const int row_b = wn * 32 + ((lane >> 4) << 3) + (lane & 7);             \
    const uint32_t b_base = (uint32_t)row_b * GROW_B +                       \
        (((((uint32_t)lane >> 3) & 1) ^ ((uint32_t)row_b & 7)) << 4);

// ---------------------------------------------------------------------------
// Persistent NT fp16 GEMM (proj): C = Ah @ Bh + bias (fp32 out)
// Tiles: (EMB/128) x (M/128); grid-stride over linear tile id.
// ---------------------------------------------------------------------------
__global__ void __launch_bounds__(256, 2) gemm_f16(
    const __half* __restrict__ Ah, const __half* __restrict__ Bh,
    float* __restrict__ C, const float* __restrict__ bias,
    int K, int lda, int ldb, int ldc, int tilesN, int tilesTotal)
{
    extern __shared__ char smem[];
    __shared__ float s_bias[128];

    GEMM_IDX_SETUP()

    for (int tix = blockIdx.x; tix < tilesTotal; tix += gridDim.x) {
        __syncthreads();   // previous tile fully done (s_bias / smem reuse)
        const long long bm = (long long)(tix / tilesN) * 128;
        const long long bn = (long long)(tix % tilesN) * 128;
        if (tid < 128) s_bias[tid] = bias[bn + tid];

        GEMM_MAINLOOP(Ah, Bh, K, lda, ldb)

        #pragma unroll
        for (int mt = 0; mt < 4; ++mt) {
            const long long r = bm + wm * 64 + mt * 16 + (lane >> 2);
            float* row0 = C + r * ldc + bn + wn * 32;
            float* row1 = row0 + 8LL * ldc;
            #pragma unroll
            for (int n8 = 0; n8 < 4; ++n8) {
                const int c = n8 * 8 + ((lane & 3) << 1);
                const float b0 = s_bias[wn * 32 + c];
                const float b1 = s_bias[wn * 32 + c + 1];
                float2 v0, v1;
                v0.x = acc[mt][n8][0] + b0;
                v0.y = acc[mt][n8][1] + b1;
                v1.x = acc[mt][n8][2] + b0;
                v1.y = acc[mt][n8][3] + b1;
                *(float2*)(row0 + c) = v0;
                *(float2*)(row1 + c) = v1;
            }
        }
    }
}

// ---------------------------------------------------------------------------
// Persistent QKV GEMM with fused RoPE / V-transpose epilogue.
// Tiles: 48 (N) x 32 (M) = 1536; grid-stride. Epilogue staging buffer
// aliases pipeline smem -> the loop-top __syncthreads() is load-bearing.
// ---------------------------------------------------------------------------
__global__ void __launch_bounds__(256, 2) gemm_qkv(
    const __half* __restrict__ Ah, const __half* __restrict__ Bh,
    const float* __restrict__ bias)
{
    extern __shared__ char smem[];
    __shared__ float s_bias[128];

    GEMM_IDX_SETUP()

    for (int tix = blockIdx.x; tix < 1536; tix += gridDim.x) {
        __syncthreads();   // previous epilogue done before new prologue writes
        const long long bm = (long long)(tix / 48) * 128;
        const long long bn = (long long)(tix % 48) * 128;
        if (tid < 128) s_bias[tid] = bias[bn + tid];

        GEMM_MAINLOOP(Ah, Bh, EMB, EMB, EMB)

        // ---- stage biased fp32 tile into smem [128][129] ----
        __syncthreads();
        float* st = (float*)smem;
        #pragma unroll
        for (int mt = 0; mt < 4; ++mt) {
            const int rr = wm * 64 + mt * 16 + (lane >> 2);
            #pragma unroll
            for (int n8 = 0; n8 < 4; ++n8) {
                const int c = wn * 32 + n8 * 8 + ((lane & 3) << 1);
                const float b0 = s_bias[c], b1 = s_bias[c + 1];
                st[rr * 129 + c]           = acc[mt][n8][0] + b0;
                st[rr * 129 + c + 1]       = acc[mt][n8][1] + b1;
                st[(rr + 8) * 129 + c]     = acc[mt][n8][2] + b0;
                st[(rr + 8) * 129 + c + 1] = acc[mt][n8][3] + b1;
            }
        }
        __syncthreads();

        if (bn < 2 * EMB) {
            #pragma unroll
            for (int it = 0; it < 32; ++it) {
                const int idx = it * 256 + tid;
                const int r = idx >> 6, j = idx & 63;
                const float v0 = st[r * 129 + j];
                const float v1 = st[r * 129 + j + 64];
                const long long tix2 = (bm + r) * 64 + j;
                const float cs = g_cos[tix2];
                const float sn = g_sin[tix2];
                const long long o = (bm + r) * (long long)E3 + bn;
                g_qkh[o + j]      = __float2half_rn(v0 * cs - v1 * sn);
                g_qkh[o + j + 64] = __float2half_rn(v1 * cs + v0 * sn);
            }
        } else {
            const int hh = (int)((bn - 2 * EMB) >> 7);
            const int bb = (int)(bm >> 11);
            const int lbase = (int)(bm & (SEQ - 1));
            const long long vbase =
                ((long long)(bb * NH + hh) * HDIM) * SEQ + lbase;
            #pragma unroll
            for (int it = 0; it < 64; ++it) {
                const int idx = it * 256 + tid;
                const int d = idx >> 7, l = idx & 127;
                g_vth[vbase + (long long)d * SEQ + l] =
                    __float2half_rn(st[l * 129 + d]);
            }
        }
    }
}

// ---------------------------------------------------------------------------
// Merged prep kernel: rope tables | x convert | W_attn^T | W_proj^T
// ---------------------------------------------------------------------------
__global__ void __launch_bounds__(256) prep_kernel(
    const float* __restrict__ x, const float* __restrict__ W_attn,
    const float* __restrict__ W_proj, const int* __restrict__ pos)
{
    const int bx = blockIdx.x;
    const int tid = threadIdx.x;

    if (bx < 1024) {
        const int idx = bx * 256 + tid;
        const int j  = idx & 63;
        const int bl = idx >> 6;
        const float p = (float)pos[bl];
        const float invf = expf(-(float)j * 0.14391156831212787f);
        float s, c;
        sincosf(p * invf, &s, &c);
        g_cos[idx] = c;
        g_sin[idx] = s;
        return;
    }
    if (bx < 9216) {
        const int i = (bx - 1024) * 256 + tid;
        const float4 v = ((const float4*)x)[i];
        __half2 h0, h1;
        h0.x = __float2half_rn(v.x); h0.y = __float2half_rn(v.y);
        h1.x = __float2half_rn(v.z); h1.y = __float2half_rn(v.w);
        ((__half2*)g_xh)[2 * i]     = h0;
        ((__half2*)g_xh)[2 * i + 1] = h1;
        return;
    }
    __shared__ float tile[32][33];
    const int tx = tid & 31, ty = tid >> 5;
    const float* src;
    __half* dst;
    int Kd, Nd, n0, k0;
    if (bx < 21504) {
        const int f = bx - 9216;
        src = W_attn; dst = g_wah; Kd = EMB; Nd = E3;
        n0 = (f % 192) * 32; k0 = (f / 192) * 32;
    } else {
        const int f = bx - 21504;
        src = W_proj; dst = g_wph; Kd = EMB; Nd = EMB;
        n0 = (f % 64) * 32; k0 = (f / 64) * 32;
    }
    #pragma unroll
    for (int j = 0; j < 32; j += 8)
        tile[ty + j][tx] = src[(long long)(k0 + ty + j) * Nd + n0 + tx];
    __syncthreads();
    #pragma unroll
    for (int j = 0; j < 32; j += 8) {
        const float v = tile[tx][ty + j];
        const long long o = (long long)(n0 + ty + j) * Kd + k0 + tx;
        dst[o] = __float2half_rn(v);
    }
}

// ---------------------------------------------------------------------------
// exp + pack 4 fp32 -> fp16 hi A-fragments, accumulate row sums
// ---------------------------------------------------------------------------
__device__ __forceinline__ void exp_pack4h(const float* s, float& lsum0,
                                           float& lsum1, uint32_t* ph)
{
    const float e0 = __expf(s[0] * SM_SCALE);
    const float e1 = __expf(s[1] * SM_SCALE);
    const float e2 = __expf(s[2] * SM_SCALE);
    const float e3 = __expf(s[3] * SM_SCALE);
    lsum0 += e0 + e1;
    lsum1 += e2 + e3;
    asm("cvt.rn.f16x2.f32 %0, %1, %2;" : "=r"(ph[0]) : "f"(e1), "f"(e0));
    asm("cvt.rn.f16x2.f32 %0, %1, %2;" : "=r"(ph[1]) : "f"(e3), "f"(e2));
}

// ---------------------------------------------------------------------------
// Fused flash attention, fp16, 512 threads, 256 q-rows per CTA (unchanged).
// ---------------------------------------------------------------------------
#define FA_SMEM (192 * 1024)

__global__ void __launch_bounds__(512) flash_kernel()
{
    extern __shared__ char smem[];
    const int z = blockIdx.y;
    const int b = z >> 4, h = z & 15;
    const int bq = blockIdx.x * 256;
    const int tid = threadIdx.x;
    const int wid = tid >> 5, lane = tid & 31;

    const uint32_t sb = smem_u32(smem);
    const uint32_t BQ0 = sb,            BQ1 = sb + 32768;
    const uint32_t K0  = sb + 65536,    K1  = sb + 98304;
    const uint32_t V0  = sb + 131072,   V1  = sb + 163840;

    const int lr = tid >> 2;
    const int cc = tid & 3;
    const uint32_t swsel = (uint32_t)((lr & 3) ^ ((lr >> 2) & 1));
    const uint32_t d0 = (uint32_t)lr * 64 + ((cc ^ swsel) << 4);

    const long long zq = (long long)b * SEQ * E3 + (long long)h * HDIM;
    const __half* Qh = g_qkh + zq;
    const __half* Kh = Qh + EMB;
    const __half* Vh = g_vth + (long long)z * HDIM * SEQ;

#define FA_LD1(buf, G, rowbase, ldx, colbase)                              \
    do { _Pragma("unroll")                                                 \
        for (int kc = 0; kc < 4; ++kc) {                                   \
            const long long off = ((long long)(rowbase) + lr) * (ldx)      \
                                  + (colbase) + kc * 32 + cc * 8;          \
            CP16((buf) + kc * 8192 + d0, (G) + off);                       \
        }                                                                  \
    } while (0)

    FA_LD1(BQ0, Qh, bq, E3, 0);
    FA_LD1(BQ1, Qh, bq + 128, E3, 0);
    CP_COMMIT();
    FA_LD1(K0, Kh, 0, E3, 0);
    CP_COMMIT();
    FA_LD1(V0, Vh, 0, SEQ, 0);
    CP_COMMIT();

    CP_WAIT2();
    __syncthreads();

    const int inner = (wid & 7) * 16 + (lane & 15);
    const uint32_t qbuf = (wid < 8) ? BQ0 : BQ1;
    const uint32_t swA = (uint32_t)((inner & 3) ^ ((inner >> 2) & 1));
    const uint32_t a_base =
        (uint32_t)inner * 64 + ((((uint32_t)lane >> 4) ^ swA) << 4);
    uint32_t qfh[8][4];
    #pragma unroll
    for (int k16 = 0; k16 < 8; ++k16) {
        const uint32_t ad = (uint32_t)(k16 >> 1) * 8192 +
                            (a_base ^ ((uint32_t)(k16 & 1) << 5));
        ldsm_x4(qfh[k16], qbuf + ad);
    }

    const int row_b = ((lane >> 4) << 3) + (lane & 7);
    const uint32_t swB = (uint32_t)((row_b & 3) ^ ((row_b >> 2) & 1));
    const uint32_t b_base =
        (uint32_t)row_b * 64 + (((((uint32_t)lane >> 3) & 1) ^ swB) << 4);

    float yacc[16][4];
    #pragma unroll
    for (int i = 0; i < 16; ++i)
        #pragma unroll
        for (int j = 0; j < 4; ++j) yacc[i][j] = 0.f;
    float lsum0 = 0.f, lsum1 = 0.f;

    for (int i = 0; i < 16; ++i) {
        const uint32_t curK = (i & 1) ? K1 : K0;
        const uint32_t curV = (i & 1) ? V1 : V0;

        CP_WAIT0();
        __syncthreads();

        if (i < 15) {
            FA_LD1((i & 1) ? K0 : K1, Kh, 128 * (i + 1), E3, 0);
            CP_COMMIT();
            FA_LD1((i & 1) ? V0 : V1, Vh, 0, SEQ, 128 * (i + 1));
            CP_COMMIT();
        }

        #pragma unroll
        for (int c = 0; c < 8; ++c) {
            float s0[4] = {0.f, 0.f, 0.f, 0.f};
            float s1[4] = {0.f, 0.f, 0.f, 0.f};
            #pragma unroll
            for (int k16 = 0; k16 < 8; ++k16) {
                uint32_t fh[4];
                const uint32_t ad = (uint32_t)(k16 >> 1) * 8192 +
                    ((b_base + (uint32_t)c * 1024u) ^ ((uint32_t)(k16 & 1) << 5));
                ldsm_x4(fh, curK + ad);
                mma16816h(s0, qfh[k16], fh);
                mma16816h(s1, qfh[k16], fh + 2);
            }
            uint32_t ph[4];
            exp_pack4h(s0, lsum0, lsum1, &ph[0]);
            exp_pack4h(s1, lsum0, lsum1, &ph[2]);
            #pragma unroll
            for (int nb = 0; nb < 8; ++nb) {
                uint32_t fv[4];
                const uint32_t ad = (uint32_t)(c >> 1) * 8192 +
                    ((b_base + (uint32_t)nb * 1024u) ^ ((uint32_t)(c & 1) << 5));
                ldsm_x4(fv, curV + ad);
                mma16816h(yacc[2 * nb],     ph, fv);
                mma16816h(yacc[2 * nb + 1], ph, fv + 2);
            }
        }
    }
#undef FA_LD1

    lsum0 += __shfl_xor_sync(0xffffffffu, lsum0, 1);
    lsum0 += __shfl_xor_sync(0xffffffffu, lsum0, 2);
    lsum1 += __shfl_xor_sync(0xffffffffu, lsum1, 1);
    lsum1 += __shfl_xor_sync(0xffffffffu, lsum1, 2);
    const float inv0 = 1.0f / lsum0;
    const float inv1 = 1.0f / lsum1;

    const int q0 = bq + wid * 16 + (lane >> 2);
    const long long ob = (long long)b * SEQ * EMB + (long long)h * HDIM;
    #pragma unroll
    for (int T = 0; T < 16; ++T) {
        const int dcol = T * 8 + ((lane & 3) << 1);
        __half2 hh0, hh1;
        hh0.x = __float2half_rn(yacc[T][0] * inv0);
        hh0.y = __float2half_rn(yacc[T][1] * inv0);
        hh1.x = __float2half_rn(yacc[T][2] * inv1);
        hh1.y = __float2half_rn(yacc[T][3] * inv1);
        const long long o0 = ob + (long long)q0 * EMB + dcol;
        const long long o1 = o0 + 8LL * EMB;
        *(__half2*)(g_yh + o0) = hh0;
        *(__half2*)(g_yh + o1) = hh1;
    }
}

// ---------------------------------------------------------------------------
// Launch sequence
// ---------------------------------------------------------------------------
extern "C" void kernel_launch(void* const* d_in, const int* in_sizes, int n_in,
                              void* d_out, int out_size)
{
    const float* x      = (const float*)d_in[0];
    const int*   pos    = (const int*)  d_in[1];
    const float* W_attn = (const float*)d_in[2];
    const float* b_attn = (const float*)d_in[3];
    const float* W_proj = (const float*)d_in[4];
    const float* b_proj = (const float*)d_in[5];
    float* out = (float*)d_out;

    __half *xh, *wah, *yh, *wph;
    cudaGetSymbolAddress((void**)&xh,  g_xh);
    cudaGetSymbolAddress((void**)&wah, g_wah);
    cudaGetSymbolAddress((void**)&yh,  g_yh);
    cudaGetSymbolAddress((void**)&wph, g_wph);

    cudaFuncSetAttribute(gemm_f16,
                         cudaFuncAttributeMaxDynamicSharedMemorySize, GSMEM);
    cudaFuncSetAttribute(gemm_qkv,
                         cudaFuncAttributeMaxDynamicSharedMemorySize, GSMEM);
    cudaFuncSetAttribute(flash_kernel,
                         cudaFuncAttributeMaxDynamicSharedMemorySize, FA_SMEM);

    // 0. merged prep: rope tables + x convert + weight transposes
    prep_kernel<<<25600, 256>>>(x, W_attn, W_proj, pos);

    // 1. qkv GEMM (persistent, single product, BK=64) + fused epilogue
    gemm_qkv<<<PERSIST_CTAS, 256, GSMEM>>>(xh, wah, b_attn);

    // 2. fused attention (fp16, 512 thr, 256 q-rows/CTA) -> yh
    flash_kernel<<<dim3(SEQ / 256, BATCH * NH, 1), 512, FA_SMEM>>>();

    // 3. out = y @ W_proj + b (persistent, single product, BK=64)
    gemm_f16<<<PERSIST_CTAS, 256, GSMEM>>>(
        yh, wph, out, b_proj, EMB, EMB, EMB, EMB, EMB / 128, 512);
}

// round 16
// speedup vs baseline: 1.0500x; 1.0500x over previous
#include <cuda_runtime.h>
#include <cuda_fp16.h>
#include <cstdint>
#include <math.h>

// Problem constants
#define BATCH 2
#define SEQ   2048
#define EMB   2048
#define NH    16
#define HDIM  128
#define E3    6144

#define SM_SCALE 0.08838834764831845f

// ---------------------------------------------------------------------------
// Scratch (__device__ globals; allocation-free rule)
// ---------------------------------------------------------------------------
__device__ __half g_xh[(size_t)BATCH * SEQ * EMB];
__device__ __half g_wah[(size_t)E3 * EMB];                         // W_attn^T hi
__device__ __half g_qkh[(size_t)BATCH * SEQ * E3];                 // q hi | k hi
__device__ __half g_vth[(size_t)BATCH * NH * HDIM * SEQ];          // V^T hi
__device__ __half g_yh[(size_t)BATCH * SEQ * EMB];
__device__ __half g_wph[(size_t)EMB * EMB];                        // W_proj^T hi
__device__ float  g_cos[(size_t)BATCH * SEQ * 64];                 // RoPE tables
__device__ float  g_sin[(size_t)BATCH * SEQ * 64];

// ---------------------------------------------------------------------------
// PTX helpers (arch-generic: cp.async, ldmatrix, mma.sync)
// ---------------------------------------------------------------------------
__device__ __forceinline__ uint32_t smem_u32(const void* p) {
    uint32_t a;
    asm("{ .reg .u64 t; cvta.to.shared.u64 t, %1; cvt.u32.u64 %0, t; }"
        : "=r"(a) : "l"(p));
    return a;
}
#define CP16(dst, src) \
    asm volatile("cp.async.cg.shared.global [%0], [%1], 16;" :: "r"(dst), "l"(src))
#define CP_COMMIT() asm volatile("cp.async.commit_group;" ::: "memory")
#define CP_WAIT0()  asm volatile("cp.async.wait_group 0;" ::: "memory")
#define CP_WAIT1()  asm volatile("cp.async.wait_group 1;" ::: "memory")
#define CP_WAIT2()  asm volatile("cp.async.wait_group 2;" ::: "memory")

__device__ __forceinline__ void ldsm_x4(uint32_t* r, uint32_t a) {
    asm volatile("ldmatrix.sync.aligned.m8n8.x4.shared.b16 {%0,%1,%2,%3}, [%4];"
        : "=r"(r[0]), "=r"(r[1]), "=r"(r[2]), "=r"(r[3]) : "r"(a));
}
__device__ __forceinline__ void mma16816h(float* d, const uint32_t* a,
                                          const uint32_t* b) {
    asm volatile(
        "mma.sync.aligned.m16n8k16.row.col.f32.f16.f16.f32 "
        "{%0,%1,%2,%3}, {%4,%5,%6,%7}, {%8,%9}, {%0,%1,%2,%3};"
        : "+f"(d[0]), "+f"(d[1]), "+f"(d[2]), "+f"(d[3])
        : "r"(a[0]), "r"(a[1]), "r"(a[2]), "r"(a[3]), "r"(b[0]), "r"(b[1]));
}

// ---------------------------------------------------------------------------
// GEMM tile geometry (BK=64): 128 rows x 64 fp16 = 128B rows.
// Swizzle: chunk' = chunk ^ (row & 7).
// ---------------------------------------------------------------------------
#define GROW_B  128
#define GTILE_B 16384
#define STB     (2 * GTILE_B)        // stage bytes (Ah, Bh) = 32 KB
#define GSMEM   (3 * STB)            // 96 KB; also >= 128*129*4 epilogue staging

// ===========================================================================
// Shared GEMM mainloop (single product Ah*Bh, BK=64): computes acc[4][4][4]
// ===========================================================================
#define GEMM_MAINLOOP(Ah, Bh, K, lda, ldb)                                   \
    const long long ldaL = (lda), ldbL = (ldb);                              \
    const int lr0 = tid >> 3;                                                \
    const int lc  = tid & 7;                                                 \
    const uint32_t ldst =                                                    \
        (uint32_t)lr0 * GROW_B + (((uint32_t)lc ^ (lr0 & 7)) << 4);          \
    const __half* pA = (Ah) + (bm + lr0) * ldaL + lc * 8;                    \
    const __half* pB = (Bh) + (bn + lr0) * ldbL + lc * 8;                    \
    const int nt = (K) >> 6;                                                 \
    ISSUE_STAGE(sb);                                                         \
    CP_COMMIT();                                                             \
    ISSUE_STAGE(sb + STB);                                                   \
    CP_COMMIT();                                                             \
    float acc[4][4][4];                                                      \
    _Pragma("unroll")                                                        \
    for (int i = 0; i < 4; ++i)                                              \
        _Pragma("unroll")                                                    \
        for (int j = 0; j < 4; ++j)                                          \
            _Pragma("unroll")                                                \
            for (int k = 0; k < 4; ++k) acc[i][j][k] = 0.f;                  \
    const int row_a = wm * 64 + (lane & 15);                                 \
    const uint32_t a_base = (uint32_t)row_a * GROW_B +                       \
        ((((uint32_t)lane >> 4) ^ ((uint32_t)row_a & 7)) << 4);              \
    const int row_b = wn * 32 + ((lane >> 4) << 3) + (lane & 7);             \
    const uint32_t b_base = (uint32_t)row_b * GROW_B +                       \
        (((((uint32_t)lane >> 3) & 1) ^ ((uint32_t)row_b & 7)) << 4);        \
    uint32_t cur_st = sb;                                                    \
    uint32_t iss_st = sb + 2 * STB;                                          \
    for (int t = 0; t < nt; ++t) {                                           \
        CP_WAIT1();                                                          \
        __syncthreads();                                                     \
        if (t + 2 < nt) ISSUE_STAGE(iss_st);                                 \
        CP_COMMIT();                                                         \
        const uint32_t pAs = cur_st, pBs = cur_st + GTILE_B;                 \
        _Pragma("unroll")                                                    \
        for (int k16 = 0; k16 < 4; ++k16) {                                  \
            const uint32_t kx = (uint32_t)(k16 << 5);                        \
            uint32_t fBh[2][4];                                              \
            _Pragma("unroll")                                                \
            for (int bt = 0; bt < 2; ++bt)                                   \
                ldsm_x4(fBh[bt], pBs + ((b_base + bt * (16 * GROW_B)) ^ kx));\
            _Pragma("unroll")                                                \
            for (int mt = 0; mt < 4; ++mt) {                                 \
                uint32_t fAh[4];                                             \
                ldsm_x4(fAh, pAs + ((a_base + mt * (16 * GROW_B)) ^ kx));    \
                _Pragma("unroll")                                            \
                for (int n8 = 0; n8 < 4; ++n8) {                             \
                    const uint32_t* bh = &fBh[n8 >> 1][(n8 & 1) << 1];       \
                    mma16816h(acc[mt][n8], fAh, bh);                         \
                }                                                            \
            }                                                                \
        }                                                                    \
        uint32_t nxt = cur_st + STB;                                         \
        if (nxt >= sb + 3 * STB) nxt = sb;                                   \
        cur_st = nxt;                                                        \
        nxt = iss_st + STB;                                                  \
        if (nxt >= sb + 3 * STB) nxt = sb;                                   \
        iss_st = nxt;                                                        \
    }

#define ISSUE_STAGE(st)                                                      \
    do {                                                                     \
        _Pragma("unroll")                                                    \
        for (int jj = 0; jj < 4; ++jj) {                                     \
            CP16((st) + ldst + jj * (32 * GROW_B), pA + jj * 32LL * ldaL);   \
            CP16((st) + GTILE_B + ldst + jj * (32 * GROW_B),                 \
                 pB + jj * 32LL * ldbL);                                     \
        }                                                                    \
        pA += 64; pB += 64;                                                  \
    } while (0)

// ---------------------------------------------------------------------------
// Generic NT fp16 GEMM (proj): C = Ah @ Bh + bias (fp32 out)
// ---------------------------------------------------------------------------
__global__ void __launch_bounds__(256, 2) gemm_f16(
    const __half* __restrict__ Ah, const __half* __restrict__ Bh,
    float* __restrict__ C, const float* __restrict__ bias)
{
    extern __shared__ char smem[];
    __shared__ float s_bias[128];

    const int tid  = threadIdx.x;
    const int wid  = tid >> 5, lane = tid & 31;
    const int wm   = wid & 1;
    const int wn   = wid >> 1;
    const long long bm = (long long)blockIdx.y * 128;
    const long long bn = (long long)blockIdx.x * 128;
    const uint32_t sb = smem_u32(smem);

    if (tid < 128) s_bias[tid] = bias[bn + tid];

    GEMM_MAINLOOP(Ah, Bh, EMB, EMB, EMB)

    #pragma unroll
    for (int mt = 0; mt < 4; ++mt) {
        const long long r = bm + wm * 64 + mt * 16 + (lane >> 2);
        float* row0 = C + r * EMB + bn + wn * 32;
        float* row1 = row0 + 8LL * EMB;
        #pragma unroll
        for (int n8 = 0; n8 < 4; ++n8) {
            const int c = n8 * 8 + ((lane & 3) << 1);
            const float b0 = s_bias[wn * 32 + c];
            const float b1 = s_bias[wn * 32 + c + 1];
            float2 v0, v1;
            v0.x = acc[mt][n8][0] + b0;
            v0.y = acc[mt][n8][1] + b1;
            v1.x = acc[mt][n8][2] + b0;
            v1.y = acc[mt][n8][3] + b1;
            *(float2*)(row0 + c) = v0;
            *(float2*)(row1 + c) = v1;
        }
    }
}

// ---------------------------------------------------------------------------
// QKV GEMM with fused RoPE (table-based) / V-transpose epilogue.
// ---------------------------------------------------------------------------
__global__ void __launch_bounds__(256, 2) gemm_qkv(
    const __half* __restrict__ Ah, const __half* __restrict__ Bh,
    const float* __restrict__ bias)
{
    extern __shared__ char smem[];
    __shared__ float s_bias[128];

    const int tid  = threadIdx.x;
    const int wid  = tid >> 5, lane = tid & 31;
    const int wm   = wid & 1;
    const int wn   = wid >> 1;
    const long long bm = (long long)blockIdx.y * 128;
    const long long bn = (long long)blockIdx.x * 128;
    const uint32_t sb = smem_u32(smem);

    if (tid < 128) s_bias[tid] = bias[bn + tid];

    GEMM_MAINLOOP(Ah, Bh, EMB, EMB, EMB)

    // ---- stage biased fp32 tile into smem [128][129] ----
    __syncthreads();
    float* st = (float*)smem;
    #pragma unroll
    for (int mt = 0; mt < 4; ++mt) {
        const int rr = wm * 64 + mt * 16 + (lane >> 2);
        #pragma unroll
        for (int n8 = 0; n8 < 4; ++n8) {
            const int c = wn * 32 + n8 * 8 + ((lane & 3) << 1);
            const float b0 = s_bias[c], b1 = s_bias[c + 1];
            st[rr * 129 + c]           = acc[mt][n8][0] + b0;
            st[rr * 129 + c + 1]       = acc[mt][n8][1] + b1;
            st[(rr + 8) * 129 + c]     = acc[mt][n8][2] + b0;
            st[(rr + 8) * 129 + c + 1] = acc[mt][n8][3] + b1;
        }
    }
    __syncthreads();

    if (bn < 2 * EMB) {
        #pragma unroll
        for (int it = 0; it < 32; ++it) {
            const int idx = it * 256 + tid;
            const int r = idx >> 6, j = idx & 63;
            const float v0 = st[r * 129 + j];
            const float v1 = st[r * 129 + j + 64];
            const long long tix = (bm + r) * 64 + j;
            const float cs = g_cos[tix];
            const float sn = g_sin[tix];
            const long long o = (bm + r) * (long long)E3 + bn;
            g_qkh[o + j]      = __float2half_rn(v0 * cs - v1 * sn);
            g_qkh[o + j + 64] = __float2half_rn(v1 * cs + v0 * sn);
        }
    } else {
        const int hh = (int)((bn - 2 * EMB) >> 7);
        const int bb = (int)(bm >> 11);
        const int lbase = (int)(bm & (SEQ - 1));
        const long long vbase =
            ((long long)(bb * NH + hh) * HDIM) * SEQ + lbase;
        #pragma unroll
        for (int it = 0; it < 64; ++it) {
            const int idx = it * 256 + tid;
            const int d = idx >> 7, l = idx & 127;
            g_vth[vbase + (long long)d * SEQ + l] =
                __float2half_rn(st[l * 129 + d]);
        }
    }
}

// ---------------------------------------------------------------------------
// Merged prep kernel: rope tables | x convert | W_attn^T | W_proj^T
// Block ranges: [0,1024) rope, [1024,9216) conv, [9216,21504) wa, [21504,25600) wp
// ---------------------------------------------------------------------------
__global__ void __launch_bounds__(256) prep_kernel(
    const float* __restrict__ x, const float* __restrict__ W_attn,
    const float* __restrict__ W_proj, const int* __restrict__ pos)
{
    const int bx = blockIdx.x;
    const int tid = threadIdx.x;

    if (bx < 1024) {
        // RoPE tables
        const int idx = bx * 256 + tid;
        const int j  = idx & 63;
        const int bl = idx >> 6;
        const float p = (float)pos[bl];
        const float invf = expf(-(float)j * 0.14391156831212787f);
        float s, c;
        sincosf(p * invf, &s, &c);
        g_cos[idx] = c;
        g_sin[idx] = s;
        return;
    }
    if (bx < 9216) {
        // x fp32 -> fp16 (float4 per thread, one 8B store)
        const int i = (bx - 1024) * 256 + tid;
        const float4 v = ((const float4*)x)[i];
        __half2 h2[2];
        h2[0].x = __float2half_rn(v.x); h2[0].y = __float2half_rn(v.y);
        h2[1].x = __float2half_rn(v.z); h2[1].y = __float2half_rn(v.w);
        ((uint2*)g_xh)[i] = *(uint2*)h2;
        return;
    }
    // transpose-convert weights
    __shared__ float tile[32][33];
    const int tx = tid & 31, ty = tid >> 5;
    const float* src;
    __half* dst;
    int Kd, Nd, n0, k0;
    if (bx < 21504) {
        const int f = bx - 9216;            // 192 x 64
        src = W_attn; dst = g_wah; Kd = EMB; Nd = E3;
        n0 = (f % 192) * 32; k0 = (f / 192) * 32;
    } else {
        const int f = bx - 21504;           // 64 x 64
        src = W_proj; dst = g_wph; Kd = EMB; Nd = EMB;
        n0 = (f % 64) * 32; k0 = (f / 64) * 32;
    }
    #pragma unroll
    for (int j = 0; j < 32; j += 8)
        tile[ty + j][tx] = src[(long long)(k0 + ty + j) * Nd + n0 + tx];
    __syncthreads();
    #pragma unroll
    for (int j = 0; j < 32; j += 8) {
        const float v = tile[tx][ty + j];
        const long long o = (long long)(n0 + ty + j) * Kd + k0 + tx;
        dst[o] = __float2half_rn(v);
    }
}

// ---------------------------------------------------------------------------
// exp + pack 4 fp32 -> fp16 hi A-fragments, accumulate row sums
// ---------------------------------------------------------------------------
__device__ __forceinline__ void exp_pack4h(const float* s, float& lsum0,
                                           float& lsum1, uint32_t* ph)
{
    const float e0 = __expf(s[0] * SM_SCALE);
    const float e1 = __expf(s[1] * SM_SCALE);
    const float e2 = __expf(s[2] * SM_SCALE);
    const float e3 = __expf(s[3] * SM_SCALE);
    lsum0 += e0 + e1;
    lsum1 += e2 + e3;
    asm("cvt.rn.f16x2.f32 %0, %1, %2;" : "=r"(ph[0]) : "f"(e1), "f"(e0));
    asm("cvt.rn.f16x2.f32 %0, %1, %2;" : "=r"(ph[1]) : "f"(e3), "f"(e2));
}

// ---------------------------------------------------------------------------
// Fused flash attention, fp16, 512 threads, 256 q-rows per CTA.
// 16 warps (4/SMSP), grid (8, 32) = 256 CTAs. Per-chunk fused S->exp->PV.
// SMEM: Q0|Q1 (32K each) + K0|K1 (32K each) + V0|V1 (32K each) = 192 KB.
// ---------------------------------------------------------------------------
#define FA_SMEM (192 * 1024)

__global__ void __launch_bounds__(512) flash_kernel()
{
    extern __shared__ char smem[];
    const int z = blockIdx.y;
    const int b = z >> 4, h = z & 15;
    const int bq = blockIdx.x * 256;
    const int tid = threadIdx.x;
    const int wid = tid >> 5, lane = tid & 31;

    const uint32_t sb = smem_u32(smem);
    const uint32_t BQ0 = sb,            BQ1 = sb + 32768;
    const uint32_t K0  = sb + 65536,    K1  = sb + 98304;
    const uint32_t V0  = sb + 131072,   V1  = sb + 163840;

    const int lr = tid >> 2;
    const int cc = tid & 3;
    const uint32_t swsel = (uint32_t)((lr & 3) ^ ((lr >> 2) & 1));
    const uint32_t d0 = (uint32_t)lr * 64 + ((cc ^ swsel) << 4);

    const long long zq = (long long)b * SEQ * E3 + (long long)h * HDIM;
    const __half* Qh = g_qkh + zq;
    const __half* Kh = Qh + EMB;
    const __half* Vh = g_vth + (long long)z * HDIM * SEQ;

#define FA_LD1(buf, G, rowbase, ldx, colbase)                              \
    do { _Pragma("unroll")                                                 \
        for (int kc = 0; kc < 4; ++kc) {                                   \
            const long long off = ((long long)(rowbase) + lr) * (ldx)      \
                                  + (colbase) + kc * 32 + cc * 8;          \
            CP16((buf) + kc * 8192 + d0, (G) + off);                       \
        }                                                                  \
    } while (0)

    FA_LD1(BQ0, Qh, bq, E3, 0);
    FA_LD1(BQ1, Qh, bq + 128, E3, 0);
    CP_COMMIT();
    FA_LD1(K0, Kh, 0, E3, 0);
    CP_COMMIT();
    FA_LD1(V0, Vh, 0, SEQ, 0);
    CP_COMMIT();

    CP_WAIT2();
    __syncthreads();

    const int inner = (wid & 7) * 16 + (lane & 15);
    const uint32_t qbuf = (wid < 8) ? BQ0 : BQ1;
    const uint32_t swA = (uint32_t)((inner & 3) ^ ((inner >> 2) & 1));
    const uint32_t a_base =
        (uint32_t)inner * 64 + ((((uint32_t)lane >> 4) ^ swA) << 4);
    uint32_t qfh[8][4];
    #pragma unroll
    for (int k16 = 0; k16 < 8; ++k16) {
        const uint32_t ad = (uint32_t)(k16 >> 1) * 8192 +
                            (a_base ^ ((uint32_t)(k16 & 1) << 5));
        ldsm_x4(qfh[k16], qbuf + ad);
    }

    const int row_b = ((lane >> 4) << 3) + (lane & 7);
    const uint32_t swB = (uint32_t)((row_b & 3) ^ ((row_b >> 2) & 1));
    const uint32_t b_base =
        (uint32_t)row_b * 64 + (((((uint32_t)lane >> 3) & 1) ^ swB) << 4);

    float yacc[16][4];
    #pragma unroll
    for (int i = 0; i < 16; ++i)
        #pragma unroll
        for (int j = 0; j < 4; ++j) yacc[i][j] = 0.f;
    float lsum0 = 0.f, lsum1 = 0.f;

    for (int i = 0; i < 16; ++i) {
        const uint32_t curK = (i & 1) ? K1 : K0;
        const uint32_t curV = (i & 1) ? V1 : V0;

        CP_WAIT0();
        __syncthreads();

        if (i < 15) {
            FA_LD1((i & 1) ? K0 : K1, Kh, 128 * (i + 1), E3, 0);
            CP_COMMIT();
            FA_LD1((i & 1) ? V0 : V1, Vh, 0, SEQ, 128 * (i + 1));
            CP_COMMIT();
        }

        #pragma unroll
        for (int c = 0; c < 8; ++c) {
            float s0[4] = {0.f, 0.f, 0.f, 0.f};
            float s1[4] = {0.f, 0.f, 0.f, 0.f};
            #pragma unroll
            for (int k16 = 0; k16 < 8; ++k16) {
                uint32_t fh[4];
                const uint32_t ad = (uint32_t)(k16 >> 1) * 8192 +
                    ((b_base + (uint32_t)c * 1024u) ^ ((uint32_t)(k16 & 1) << 5));
                ldsm_x4(fh, curK + ad);
                mma16816h(s0, qfh[k16], fh);
                mma16816h(s1, qfh[k16], fh + 2);
            }
            uint32_t ph[4];
            exp_pack4h(s0, lsum0, lsum1, &ph[0]);
            exp_pack4h(s1, lsum0, lsum1, &ph[2]);
            #pragma unroll
            for (int nb = 0; nb < 8; ++nb) {
                uint32_t fv[4];
                const uint32_t ad = (uint32_t)(c >> 1) * 8192 +
                    ((b_base + (uint32_t)nb * 1024u) ^ ((uint32_t)(c & 1) << 5));
                ldsm_x4(fv, curV + ad);
                mma16816h(yacc[2 * nb],     ph, fv);
                mma16816h(yacc[2 * nb + 1], ph, fv + 2);
            }
        }
    }
#undef FA_LD1

    lsum0 += __shfl_xor_sync(0xffffffffu, lsum0, 1);
    lsum0 += __shfl_xor_sync(0xffffffffu, lsum0, 2);
    lsum1 += __shfl_xor_sync(0xffffffffu, lsum1, 1);
    lsum1 += __shfl_xor_sync(0xffffffffu, lsum1, 2);
    const float inv0 = 1.0f / lsum0;
    const float inv1 = 1.0f / lsum1;

    const int q0 = bq + wid * 16 + (lane >> 2);
    const long long ob = (long long)b * SEQ * EMB + (long long)h * HDIM;
    #pragma unroll
    for (int T = 0; T < 16; ++T) {
        const int dcol = T * 8 + ((lane & 3) << 1);
        __half2 hh0, hh1;
        hh0.x = __float2half_rn(yacc[T][0] * inv0);
        hh0.y = __float2half_rn(yacc[T][1] * inv0);
        hh1.x = __float2half_rn(yacc[T][2] * inv1);
        hh1.y = __float2half_rn(yacc[T][3] * inv1);
        const long long o0 = ob + (long long)q0 * EMB + dcol;
        const long long o1 = o0 + 8LL * EMB;
        *(__half2*)(g_yh + o0) = hh0;
        *(__half2*)(g_yh + o1) = hh1;
    }
}

// ---------------------------------------------------------------------------
// Launch sequence
// ---------------------------------------------------------------------------
extern "C" void kernel_launch(void* const* d_in, const int* in_sizes, int n_in,
                              void* d_out, int out_size)
{
    const float* x      = (const float*)d_in[0];
    const int*   pos    = (const int*)  d_in[1];
    const float* W_attn = (const float*)d_in[2];
    const float* b_attn = (const float*)d_in[3];
    const float* W_proj = (const float*)d_in[4];
    const float* b_proj = (const float*)d_in[5];
    float* out = (float*)d_out;

    __half *xh, *wah, *yh, *wph;
    cudaGetSymbolAddress((void**)&xh,  g_xh);
    cudaGetSymbolAddress((void**)&wah, g_wah);
    cudaGetSymbolAddress((void**)&yh,  g_yh);
    cudaGetSymbolAddress((void**)&wph, g_wph);

    cudaFuncSetAttribute(gemm_f16,
                         cudaFuncAttributeMaxDynamicSharedMemorySize, GSMEM);
    cudaFuncSetAttribute(gemm_qkv,
                         cudaFuncAttributeMaxDynamicSharedMemorySize, GSMEM);
    cudaFuncSetAttribute(flash_kernel,
                         cudaFuncAttributeMaxDynamicSharedMemorySize, FA_SMEM);

    // 0. merged prep: rope tables + x convert + weight transposes
    prep_kernel<<<25600, 256>>>(x, W_attn, W_proj, pos);

    // 1. qkv GEMM (single product, BK=64) + fused bias/RoPE/V-transpose
    gemm_qkv<<<dim3(E3 / 128, (BATCH * SEQ) / 128, 1), 256, GSMEM>>>(
        xh, wah, b_attn);

    // 2. fused attention (fp16, 512 thr, 256 q-rows/CTA) -> yh
    flash_kernel<<<dim3(SEQ / 256, BATCH * NH, 1), 512, FA_SMEM>>>();

    // 3. out = y @ W_proj + b (single product, BK=64)
    gemm_f16<<<dim3(EMB / 128, (BATCH * SEQ) / 128, 1), 256, GSMEM>>>(
        yh, wph, out, b_proj);
}

// round 17
// speedup vs baseline: 1.0889x; 1.0371x over previous
#include <cuda_runtime.h>
#include <cuda_fp16.h>
#include <cstdint>
#include <math.h>

// Problem constants
#define BATCH 2
#define SEQ   2048
#define EMB   2048
#define NH    16
#define HDIM  128
#define E3    6144

#define SM_SCALE 0.08838834764831845f

// ---------------------------------------------------------------------------
// Scratch (__device__ globals; allocation-free rule)
// ---------------------------------------------------------------------------
__device__ __half g_xh[(size_t)BATCH * SEQ * EMB];
__device__ __half g_wah[(size_t)E3 * EMB];                         // W_attn^T hi
__device__ __half g_qkh[(size_t)BATCH * SEQ * E3];                 // q hi | k hi
__device__ __half g_vth[(size_t)BATCH * NH * HDIM * SEQ];          // V^T hi
__device__ __half g_yh[(size_t)BATCH * SEQ * EMB];
__device__ __half g_wph[(size_t)EMB * EMB];                        // W_proj^T hi
__device__ float  g_cos[(size_t)BATCH * SEQ * 64];                 // RoPE tables
__device__ float  g_sin[(size_t)BATCH * SEQ * 64];

// ---------------------------------------------------------------------------
// PTX helpers (arch-generic: cp.async, ldmatrix, mma.sync)
// ---------------------------------------------------------------------------
__device__ __forceinline__ uint32_t smem_u32(const void* p) {
    uint32_t a;
    asm("{ .reg .u64 t; cvta.to.shared.u64 t, %1; cvt.u32.u64 %0, t; }"
        : "=r"(a) : "l"(p));
    return a;
}
#define CP16(dst, src) \
    asm volatile("cp.async.cg.shared.global [%0], [%1], 16;" :: "r"(dst), "l"(src))
#define CP_COMMIT() asm volatile("cp.async.commit_group;" ::: "memory")
#define CP_WAIT0()  asm volatile("cp.async.wait_group 0;" ::: "memory")
#define CP_WAIT1()  asm volatile("cp.async.wait_group 1;" ::: "memory")
#define CP_WAIT2()  asm volatile("cp.async.wait_group 2;" ::: "memory")

__device__ __forceinline__ void ldsm_x4(uint32_t* r, uint32_t a) {
    asm volatile("ldmatrix.sync.aligned.m8n8.x4.shared.b16 {%0,%1,%2,%3}, [%4];"
        : "=r"(r[0]), "=r"(r[1]), "=r"(r[2]), "=r"(r[3]) : "r"(a));
}
__device__ __forceinline__ void mma16816h(float* d, const uint32_t* a,
                                          const uint32_t* b) {
    asm volatile(
        "mma.sync.aligned.m16n8k16.row.col.f32.f16.f16.f32 "
        "{%0,%1,%2,%3}, {%4,%5,%6,%7}, {%8,%9}, {%0,%1,%2,%3};"
        : "+f"(d[0]), "+f"(d[1]), "+f"(d[2]), "+f"(d[3])
        : "r"(a[0]), "r"(a[1]), "r"(a[2]), "r"(a[3]), "r"(b[0]), "r"(b[1]));
}

// ---------------------------------------------------------------------------
// GEMM tile geometry (BK=64): 128 rows x 64 fp16 = 128B rows.
// Swizzle: chunk' = chunk ^ (row & 7). K = 2048 always -> nt = 32 = 3*10 + 2.
// ---------------------------------------------------------------------------
#define GROW_B  128
#define GTILE_B 16384
#define STB     (2 * GTILE_B)        // stage bytes (Ah, Bh) = 32 KB
#define GSMEM   (3 * STB)            // 96 KB; also >= 128*129*4 epilogue staging

#define ISSUE_STAGE(st)                                                      \
    do {                                                                     \
        _Pragma("unroll")                                                    \
        for (int jj = 0; jj < 4; ++jj) {                                     \
            CP16((st) + ldst + jj * (32 * GROW_B), pA + jj * 32LL * ldaL);   \
            CP16((st) + GTILE_B + ldst + jj * (32 * GROW_B),                 \
                 pB + jj * 32LL * ldbL);                                     \
        }                                                                    \
        pA += 64; pB += 64;                                                  \
    } while (0)

// Compute one BK=64 chunk out of buffer `cur` (constant address).
#define GEMM_COMPUTE(cur)                                                    \
    do {                                                                     \
        const uint32_t pAs = (cur), pBs = (cur) + GTILE_B;                   \
        _Pragma("unroll")                                                    \
        for (int k16 = 0; k16 < 4; ++k16) {                                  \
            const uint32_t kx = (uint32_t)(k16 << 5);                        \
            uint32_t fBh[2][4];                                              \
            _Pragma("unroll")                                                \
            for (int bt = 0; bt < 2; ++bt)                                   \
                ldsm_x4(fBh[bt], pBs + ((b_base + bt * (16 * GROW_B)) ^ kx));\
            _Pragma("unroll")                                                \
            for (int mt = 0; mt < 4; ++mt) {                                 \
                uint32_t fAh[4];                                             \
                ldsm_x4(fAh, pAs + ((a_base + mt * (16 * GROW_B)) ^ kx));    \
                _Pragma("unroll")                                            \
                for (int n8 = 0; n8 < 4; ++n8) {                             \
                    const uint32_t* bh = &fBh[n8 >> 1][(n8 & 1) << 1];       \
                    mma16816h(acc[mt][n8], fAh, bh);                         \
                }                                                            \
            }                                                                \
        }                                                                    \
    } while (0)

// One pipeline step: wait, sync, issue into `iss` (constant), compute `cur`.
#define GEMM_STEP(cur, iss)                                                  \
    do {                                                                     \
        CP_WAIT1();                                                          \
        __syncthreads();                                                     \
        ISSUE_STAGE(iss);                                                    \
        CP_COMMIT();                                                         \
        GEMM_COMPUTE(cur);                                                   \
    } while (0)

// Tail step: no issue.
#define GEMM_STEP_NOISSUE(cur)                                               \
    do {                                                                     \
        CP_WAIT1();                                                          \
        __syncthreads();                                                     \
        CP_COMMIT();                                                         \
        GEMM_COMPUTE(cur);                                                   \
    } while (0)

// ===========================================================================
// Shared GEMM mainloop (single product Ah*Bh, BK=64, K=2048, nt=32):
// 3x-unrolled ring with constant stage addresses; zero branches in main loop.
// ===========================================================================
#define GEMM_MAINLOOP(Ah, Bh, lda, ldb)                                      \
    const long long ldaL = (lda), ldbL = (ldb);                              \
    const int lr0 = tid >> 3;                                                \
    const int lc  = tid & 7;                                                 \
    const uint32_t ldst =                                                    \
        (uint32_t)lr0 * GROW_B + (((uint32_t)lc ^ (lr0 & 7)) << 4);          \
    const __half* pA = (Ah) + (bm + lr0) * ldaL + lc * 8;                    \
    const __half* pB = (Bh) + (bn + lr0) * ldbL + lc * 8;                    \
    ISSUE_STAGE(sb);                                                         \
    CP_COMMIT();                                                             \
    ISSUE_STAGE(sb + STB);                                                   \
    CP_COMMIT();                                                             \
    float acc[4][4][4];                                                      \
    _Pragma("unroll")                                                        \
    for (int i = 0; i < 4; ++i)                                              \
        _Pragma("unroll")                                                    \
        for (int j = 0; j < 4; ++j)                                          \
            _Pragma("unroll")                                                \
            for (int k = 0; k < 4; ++k) acc[i][j][k] = 0.f;                  \
    const int row_a = wm * 64 + (lane & 15);                                 \
    const uint32_t a_base = (uint32_t)row_a * GROW_B +                       \
        ((((uint32_t)lane >> 4) ^ ((uint32_t)row_a & 7)) << 4);              \
    const int row_b = wn * 32 + ((lane >> 4) << 3) + (lane & 7);             \
    const uint32_t b_base = (uint32_t)row_b * GROW_B +                       \
        (((((uint32_t)lane >> 3) & 1) ^ ((uint32_t)row_b & 7)) << 4);        \
    for (int tt = 0; tt < 10; ++tt) {                                        \
        GEMM_STEP(sb,           sb + 2 * STB);                               \
        GEMM_STEP(sb + STB,     sb);                                         \
        GEMM_STEP(sb + 2 * STB, sb + STB);                                   \
    }                                                                        \
    GEMM_STEP_NOISSUE(sb);                                                   \
    GEMM_STEP_NOISSUE(sb + STB);

// ---------------------------------------------------------------------------
// Generic NT fp16 GEMM (proj): C = Ah @ Bh + bias (fp32 out)
// ---------------------------------------------------------------------------
__global__ void __launch_bounds__(256, 2) gemm_f16(
    const __half* __restrict__ Ah, const __half* __restrict__ Bh,
    float* __restrict__ C, const float* __restrict__ bias)
{
    extern __shared__ char smem[];
    __shared__ float s_bias[128];

    const int tid  = threadIdx.x;
    const int wid  = tid >> 5, lane = tid & 31;
    const int wm   = wid & 1;
    const int wn   = wid >> 1;
    const long long bm = (long long)blockIdx.y * 128;
    const long long bn = (long long)blockIdx.x * 128;
    const uint32_t sb = smem_u32(smem);

    if (tid < 128) s_bias[tid] = bias[bn + tid];

    GEMM_MAINLOOP(Ah, Bh, EMB, EMB)

    #pragma unroll
    for (int mt = 0; mt < 4; ++mt) {
        const long long r = bm + wm * 64 + mt * 16 + (lane >> 2);
        float* row0 = C + r * EMB + bn + wn * 32;
        float* row1 = row0 + 8LL * EMB;
        #pragma unroll
        for (int n8 = 0; n8 < 4; ++n8) {
            const int c = n8 * 8 + ((lane & 3) << 1);
            const float b0 = s_bias[wn * 32 + c];
            const float b1 = s_bias[wn * 32 + c + 1];
            float2 v0, v1;
            v0.x = acc[mt][n8][0] + b0;
            v0.y = acc[mt][n8][1] + b1;
            v1.x = acc[mt][n8][2] + b0;
            v1.y = acc[mt][n8][3] + b1;
            *(float2*)(row0 + c) = v0;
            *(float2*)(row1 + c) = v1;
        }
    }
}

// ---------------------------------------------------------------------------
// QKV GEMM with fused RoPE (table-based) / V-transpose epilogue.
// ---------------------------------------------------------------------------
__global__ void __launch_bounds__(256, 2) gemm_qkv(
    const __half* __restrict__ Ah, const __half* __restrict__ Bh,
    const float* __restrict__ bias)
{
    extern __shared__ char smem[];
    __shared__ float s_bias[128];

    const int tid  = threadIdx.x;
    const int wid  = tid >> 5, lane = tid & 31;
    const int wm   = wid & 1;
    const int wn   = wid >> 1;
    const long long bm = (long long)blockIdx.y * 128;
    const long long bn = (long long)blockIdx.x * 128;
    const uint32_t sb = smem_u32(smem);

    if (tid < 128) s_bias[tid] = bias[bn + tid];

    GEMM_MAINLOOP(Ah, Bh, EMB, EMB)

    // ---- stage biased fp32 tile into smem [128][129] ----
    __syncthreads();
    float* st = (float*)smem;
    #pragma unroll
    for (int mt = 0; mt < 4; ++mt) {
        const int rr = wm * 64 + mt * 16 + (lane >> 2);
        #pragma unroll
        for (int n8 = 0; n8 < 4; ++n8) {
            const int c = wn * 32 + n8 * 8 + ((lane & 3) << 1);
            const float b0 = s_bias[c], b1 = s_bias[c + 1];
            st[rr * 129 + c]           = acc[mt][n8][0] + b0;
            st[rr * 129 + c + 1]       = acc[mt][n8][1] + b1;
            st[(rr + 8) * 129 + c]     = acc[mt][n8][2] + b0;
            st[(rr + 8) * 129 + c + 1] = acc[mt][n8][3] + b1;
        }
    }
    __syncthreads();

    if (bn < 2 * EMB) {
        #pragma unroll
        for (int it = 0; it < 32; ++it) {
            const int idx = it * 256 + tid;
            const int r = idx >> 6, j = idx & 63;
            const float v0 = st[r * 129 + j];
            const float v1 = st[r * 129 + j + 64];
            const long long tix = (bm + r) * 64 + j;
            const float cs = g_cos[tix];
            const float sn = g_sin[tix];
            const long long o = (bm + r) * (long long)E3 + bn;
            g_qkh[o + j]      = __float2half_rn(v0 * cs - v1 * sn);
            g_qkh[o + j + 64] = __float2half_rn(v1 * cs + v0 * sn);
        }
    } else {
        const int hh = (int)((bn - 2 * EMB) >> 7);
        const int bb = (int)(bm >> 11);
        const int lbase = (int)(bm & (SEQ - 1));
        const long long vbase =
            ((long long)(bb * NH + hh) * HDIM) * SEQ + lbase;
        #pragma unroll
        for (int it = 0; it < 64; ++it) {
            const int idx = it * 256 + tid;
            const int d = idx >> 7, l = idx & 127;
            g_vth[vbase + (long long)d * SEQ + l] =
                __float2half_rn(st[l * 129 + d]);
        }
    }
}

// ---------------------------------------------------------------------------
// Merged prep kernel: rope tables | x convert | W_attn^T | W_proj^T
// ---------------------------------------------------------------------------
__global__ void __launch_bounds__(256) prep_kernel(
    const float* __restrict__ x, const float* __restrict__ W_attn,
    const float* __restrict__ W_proj, const int* __restrict__ pos)
{
    const int bx = blockIdx.x;
    const int tid = threadIdx.x;

    if (bx < 1024) {
        const int idx = bx * 256 + tid;
        const int j  = idx & 63;
        const int bl = idx >> 6;
        const float p = (float)pos[bl];
        const float invf = expf(-(float)j * 0.14391156831212787f);
        float s, c;
        sincosf(p * invf, &s, &c);
        g_cos[idx] = c;
        g_sin[idx] = s;
        return;
    }
    if (bx < 9216) {
        const int i = (bx - 1024) * 256 + tid;
        const float4 v = ((const float4*)x)[i];
        __half2 h2[2];
        h2[0].x = __float2half_rn(v.x); h2[0].y = __float2half_rn(v.y);
        h2[1].x = __float2half_rn(v.z); h2[1].y = __float2half_rn(v.w);
        ((uint2*)g_xh)[i] = *(uint2*)h2;
        return;
    }
    __shared__ float tile[32][33];
    const int tx = tid & 31, ty = tid >> 5;
    const float* src;
    __half* dst;
    int Kd, Nd, n0, k0;
    if (bx < 21504) {
        const int f = bx - 9216;
        src = W_attn; dst = g_wah; Kd = EMB; Nd = E3;
        n0 = (f % 192) * 32; k0 = (f / 192) * 32;
    } else {
        const int f = bx - 21504;
        src = W_proj; dst = g_wph; Kd = EMB; Nd = EMB;
        n0 = (f % 64) * 32; k0 = (f / 64) * 32;
    }
    #pragma unroll
    for (int j = 0; j < 32; j += 8)
        tile[ty + j][tx] = src[(long long)(k0 + ty + j) * Nd + n0 + tx];
    __syncthreads();
    #pragma unroll
    for (int j = 0; j < 32; j += 8) {
        const float v = tile[tx][ty + j];
        const long long o = (long long)(n0 + ty + j) * Kd + k0 + tx;
        dst[o] = __float2half_rn(v);
    }
}

// ---------------------------------------------------------------------------
// exp + pack 4 fp32 -> fp16 hi A-fragments, accumulate row sums
// ---------------------------------------------------------------------------
__device__ __forceinline__ void exp_pack4h(const float* s, float& lsum0,
                                           float& lsum1, uint32_t* ph)
{
    const float e0 = __expf(s[0] * SM_SCALE);
    const float e1 = __expf(s[1] * SM_SCALE);
    const float e2 = __expf(s[2] * SM_SCALE);
    const float e3 = __expf(s[3] * SM_SCALE);
    lsum0 += e0 + e1;
    lsum1 += e2 + e3;
    asm("cvt.rn.f16x2.f32 %0, %1, %2;" : "=r"(ph[0]) : "f"(e1), "f"(e0));
    asm("cvt.rn.f16x2.f32 %0, %1, %2;" : "=r"(ph[1]) : "f"(e3), "f"(e2));
}

// ---------------------------------------------------------------------------
// Fused flash attention, fp16, 512 threads, 256 q-rows per CTA.
// i-loop unrolled x2: constant K/V buffer addresses per body.
// ---------------------------------------------------------------------------
#define FA_SMEM (192 * 1024)

__global__ void __launch_bounds__(512) flash_kernel()
{
    extern __shared__ char smem[];
    const int z = blockIdx.y;
    const int b = z >> 4, h = z & 15;
    const int bq = blockIdx.x * 256;
    const int tid = threadIdx.x;
    const int wid = tid >> 5, lane = tid & 31;

    const uint32_t sb = smem_u32(smem);
    const uint32_t BQ0 = sb,            BQ1 = sb + 32768;
    const uint32_t K0  = sb + 65536,    K1  = sb + 98304;
    const uint32_t V0  = sb + 131072,   V1  = sb + 163840;

    const int lr = tid >> 2;
    const int cc = tid & 3;
    const uint32_t swsel = (uint32_t)((lr & 3) ^ ((lr >> 2) & 1));
    const uint32_t d0 = (uint32_t)lr * 64 + ((cc ^ swsel) << 4);

    const long long zq = (long long)b * SEQ * E3 + (long long)h * HDIM;
    const __half* Qh = g_qkh + zq;
    const __half* Kh = Qh + EMB;
    const __half* Vh = g_vth + (long long)z * HDIM * SEQ;

#define FA_LD1(buf, G, rowbase, ldx, colbase)                              \
    do { _Pragma("unroll")                                                 \
        for (int kc = 0; kc < 4; ++kc) {                                   \
            const long long off = ((long long)(rowbase) + lr) * (ldx)      \
                                  + (colbase) + kc * 32 + cc * 8;          \
            CP16((buf) + kc * 8192 + d0, (G) + off);                       \
        }                                                                  \
    } while (0)

    FA_LD1(BQ0, Qh, bq, E3, 0);
    FA_LD1(BQ1, Qh, bq + 128, E3, 0);
    CP_COMMIT();
    FA_LD1(K0, Kh, 0, E3, 0);
    CP_COMMIT();
    FA_LD1(V0, Vh, 0, SEQ, 0);
    CP_COMMIT();

    CP_WAIT2();
    __syncthreads();

    const int inner = (wid & 7) * 16 + (lane & 15);
    const uint32_t qbuf = (wid < 8) ? BQ0 : BQ1;
    const uint32_t swA = (uint32_t)((inner & 3) ^ ((inner >> 2) & 1));
    const uint32_t a_base =
        (uint32_t)inner * 64 + ((((uint32_t)lane >> 4) ^ swA) << 4);
    uint32_t qfh[8][4];
    #pragma unroll
    for (int k16 = 0; k16 < 8; ++k16) {
        const uint32_t ad = (uint32_t)(k16 >> 1) * 8192 +
                            (a_base ^ ((uint32_t)(k16 & 1) << 5));
        ldsm_x4(qfh[k16], qbuf + ad);
    }

    const int row_b = ((lane >> 4) << 3) + (lane & 7);
    const uint32_t swB = (uint32_t)((row_b & 3) ^ ((row_b >> 2) & 1));
    const uint32_t b_base =
        (uint32_t)row_b * 64 + (((((uint32_t)lane >> 3) & 1) ^ swB) << 4);

    float yacc[16][4];
    #pragma unroll
    for (int i = 0; i < 16; ++i)
        #pragma unroll
        for (int j = 0; j < 4; ++j) yacc[i][j] = 0.f;
    float lsum0 = 0.f, lsum1 = 0.f;

// one KV-block body with constant buffers; issues into the OTHER pair
#define FA_BODY(curK, curV, nxtK, nxtV, i)                                   \
    do {                                                                     \
        CP_WAIT0();                                                          \
        __syncthreads();                                                     \
        if ((i) < 15) {                                                      \
            FA_LD1(nxtK, Kh, 128 * ((i) + 1), E3, 0);                        \
            CP_COMMIT();                                                     \
            FA_LD1(nxtV, Vh, 0, SEQ, 128 * ((i) + 1));                       \
            CP_COMMIT();                                                     \
        }                                                                    \
        _Pragma("unroll")                                                    \
        for (int c = 0; c < 8; ++c) {                                        \
            float s0[4] = {0.f, 0.f, 0.f, 0.f};                              \
            float s1[4] = {0.f, 0.f, 0.f, 0.f};                              \
            _Pragma("unroll")                                                \
            for (int k16 = 0; k16 < 8; ++k16) {                              \
                uint32_t fh[4];                                              \
                const uint32_t ad = (uint32_t)(k16 >> 1) * 8192 +            \
                    ((b_base + (uint32_t)c * 1024u) ^                        \
                     ((uint32_t)(k16 & 1) << 5));                            \
                ldsm_x4(fh, (curK) + ad);                                    \
                mma16816h(s0, qfh[k16], fh);                                 \
                mma16816h(s1, qfh[k16], fh + 2);                             \
            }                                                                \
            uint32_t ph[4];                                                  \
            exp_pack4h(s0, lsum0, lsum1, &ph[0]);                            \
            exp_pack4h(s1, lsum0, lsum1, &ph[2]);                            \
            _Pragma("unroll")                                                \
            for (int nb = 0; nb < 8; ++nb) {                                 \
                uint32_t fv[4];                                              \
                const uint32_t ad = (uint32_t)(c >> 1) * 8192 +              \
                    ((b_base + (uint32_t)nb * 1024u) ^                       \
                     ((uint32_t)(c & 1) << 5));                              \
                ldsm_x4(fv, (curV) + ad);                                    \
                mma16816h(yacc[2 * nb],     ph, fv);                         \
                mma16816h(yacc[2 * nb + 1], ph, fv + 2);                     \
            }                                                                \
        }                                                                    \
    } while (0)

    for (int i = 0; i < 16; i += 2) {
        FA_BODY(K0, V0, K1, V1, i);
        FA_BODY(K1, V1, K0, V0, i + 1);
    }
#undef FA_BODY
#undef FA_LD1

    lsum0 += __shfl_xor_sync(0xffffffffu, lsum0, 1);
    lsum0 += __shfl_xor_sync(0xffffffffu, lsum0, 2);
    lsum1 += __shfl_xor_sync(0xffffffffu, lsum1, 1);
    lsum1 += __shfl_xor_sync(0xffffffffu, lsum1, 2);
    const float inv0 = 1.0f / lsum0;
    const float inv1 = 1.0f / lsum1;

    const int q0 = bq + wid * 16 + (lane >> 2);
    const long long ob = (long long)b * SEQ * EMB + (long long)h * HDIM;
    #pragma unroll
    for (int T = 0; T < 16; ++T) {
        const int dcol = T * 8 + ((lane & 3) << 1);
        __half2 hh0, hh1;
        hh0.x = __float2half_rn(yacc[T][0] * inv0);
        hh0.y = __float2half_rn(yacc[T][1] * inv0);
        hh1.x = __float2half_rn(yacc[T][2] * inv1);
        hh1.y = __float2half_rn(yacc[T][3] * inv1);
        const long long o0 = ob + (long long)q0 * EMB + dcol;
        const long long o1 = o0 + 8LL * EMB;
        *(__half2*)(g_yh + o0) = hh0;
        *(__half2*)(g_yh + o1) = hh1;
    }
}

// ---------------------------------------------------------------------------
// Launch sequence
// ---------------------------------------------------------------------------
extern "C" void kernel_launch(void* const* d_in, const int* in_sizes, int n_in,
                              void* d_out, int out_size)
{
    const float* x      = (const float*)d_in[0];
    const int*   pos    = (const int*)  d_in[1];
    const float* W_attn = (const float*)d_in[2];
    const float* b_attn = (const float*)d_in[3];
    const float* W_proj = (const float*)d_in[4];
    const float* b_proj = (const float*)d_in[5];
    float* out = (float*)d_out;

    __half *xh, *wah, *yh, *wph;
    cudaGetSymbolAddress((void**)&xh,  g_xh);
    cudaGetSymbolAddress((void**)&wah, g_wah);
    cudaGetSymbolAddress((void**)&yh,  g_yh);
    cudaGetSymbolAddress((void**)&wph, g_wph);

    cudaFuncSetAttribute(gemm_f16,
                         cudaFuncAttributeMaxDynamicSharedMemorySize, GSMEM);
    cudaFuncSetAttribute(gemm_qkv,
                         cudaFuncAttributeMaxDynamicSharedMemorySize, GSMEM);
    cudaFuncSetAttribute(flash_kernel,
                         cudaFuncAttributeMaxDynamicSharedMemorySize, FA_SMEM);

    // 0. merged prep: rope tables + x convert + weight transposes
    prep_kernel<<<25600, 256>>>(x, W_attn, W_proj, pos);

    // 1. qkv GEMM (single product, BK=64, unrolled ring) + fused epilogue
    gemm_qkv<<<dim3(E3 / 128, (BATCH * SEQ) / 128, 1), 256, GSMEM>>>(
        xh, wah, b_attn);

    // 2. fused attention (fp16, 512 thr, 256 q-rows/CTA, unrolled) -> yh
    flash_kernel<<<dim3(SEQ / 256, BATCH * NH, 1), 512, FA_SMEM>>>();

    // 3. out = y @ W_proj + b (single product, BK=64, unrolled ring)
    gemm_f16<<<dim3(EMB / 128, (BATCH * SEQ) / 128, 1), 256, GSMEM>>>(
        yh, wph, out, b_proj);
}